// round 12
// baseline (speedup 1.0000x reference)
#include <cuda_runtime.h>
#include <cuda_bf16.h>
#include <cstdint>

// ---------------------------------------------------------------------------
// MetricLoss: x [1024, 64, 768] fp32 -> (loss_homo_scaled, loss_heter_scaled)
//   f = x.reshape(1024, 49152)
//   dist[j,k] = max(||f_j||^2 + ||f_k||^2 - 2 f_j.f_k, 0)
//   homo  = sum over unordered same-group pairs of dist        (groups of 8)
//   heter = sum over ORDERED diff-group pairs of max(1-dist,0)
// Strategy: bf16 Gram via mma.sync (sm_100 base: NO tcgen05), lower triangle,
// split-K=8, 5-stage cp.async pipeline with BKC=32 (deep lookahead),
// 4 warps/CTA 64x64 warp tiles, fp32 accum, deterministic reductions.
// k_convert split into 3 launches so ncu (-s 5) lands on k_gemm.
// ---------------------------------------------------------------------------

#define N_ROWS   1024
#define KDIM     49152                 // 64 * 768
#define BK_GROUP 8
#define NGROUPS  (N_ROWS / BK_GROUP)   // 128

#define BM 128
#define BN 128
#define BKC 32                         // k per stage (finer granularity)
#define STAGES 5
#define SPLITK 8
#define KSPLIT (KDIM / SPLITK)         // 6144
#define NITER  (KSPLIT / BKC)          // 192
#define NTB    (N_ROWS / BM)           // 8
#define NTILES (NTB * (NTB + 1) / 2)   // 36
#define LDA    (BKC + 8)               // smem pitch 40 elems = 80B
#define PANEL_ELEMS (BM * LDA)         // 5120 elems = 10240 B
#define SMEM_BYTES (STAGES * 2 * PANEL_ELEMS * 2)   // 102400

// Scratch (device globals: allocation-free per harness rules)
__device__ __align__(128) __nv_bfloat16 g_fbf[(size_t)N_ROWS * KDIM]; // 96 MiB
__device__ float g_sq[N_ROWS];
__device__ float g_part[(size_t)NTILES * SPLITK * BM * BN];
__device__ float g_tileloss[NTILES][2];

// ---------------------------------------------------------------------------
// K1: fp32 -> bf16 conversion + per-row squared norm (row-chunk version)
// ---------------------------------------------------------------------------
__global__ __launch_bounds__(512) void k_convert(const float* __restrict__ x,
                                                 int row_base) {
    const int row = row_base + blockIdx.x;
    const float* xr = x + (size_t)row * KDIM;
    __nv_bfloat16* fr = g_fbf + (size_t)row * KDIM;

    float s = 0.0f;
    for (int i = threadIdx.x * 4; i < KDIM; i += blockDim.x * 4) {
        float4 v = *reinterpret_cast<const float4*>(xr + i);
        s += v.x * v.x + v.y * v.y + v.z * v.z + v.w * v.w;
        __nv_bfloat162 lo = __floats2bfloat162_rn(v.x, v.y);
        __nv_bfloat162 hi = __floats2bfloat162_rn(v.z, v.w);
        uint2 packed;
        packed.x = *reinterpret_cast<uint32_t*>(&lo);
        packed.y = *reinterpret_cast<uint32_t*>(&hi);
        *reinterpret_cast<uint2*>(fr + i) = packed;
    }

    __shared__ float red[16];
    int lane = threadIdx.x & 31, warp = threadIdx.x >> 5;
    #pragma unroll
    for (int o = 16; o; o >>= 1) s += __shfl_xor_sync(0xffffffffu, s, o);
    if (lane == 0) red[warp] = s;
    __syncthreads();
    if (warp == 0) {
        float v = (lane < 16) ? red[lane] : 0.0f;
        #pragma unroll
        for (int o = 8; o; o >>= 1) v += __shfl_xor_sync(0xffffffffu, v, o);
        if (lane == 0) g_sq[row] = v;
    }
}

// ---------------------------------------------------------------------------
// K2: bf16 Gram, lower-tri tiles, split-K=8, 5-stage BKC=32 cp.async, 4 warps
// ---------------------------------------------------------------------------
__device__ __forceinline__ uint32_t smem_u32(const void* p) {
    return (uint32_t)__cvta_generic_to_shared(p);
}
__device__ __forceinline__ void cp16(uint32_t dst, const void* src) {
    asm volatile("cp.async.cg.shared.global [%0], [%1], 16;\n" :: "r"(dst), "l"(src));
}

__global__ __launch_bounds__(128, 2) void k_gemm() {
    extern __shared__ __align__(16) __nv_bfloat16 smem[];
    // stage s: A panel at s*2*PANEL_ELEMS, B panel at +PANEL_ELEMS

    const int t = blockIdx.x;       // 0..35 (lower-tri tile index)
    const int split = blockIdx.y;   // 0..7

    int bi = 0;
    while ((bi + 1) * (bi + 2) / 2 <= t) bi++;
    const int bj = t - bi * (bi + 1) / 2;

    const int row0 = bi * BM;
    const int col0 = bj * BN;
    const int k_begin = split * KSPLIT;

    const int tid  = threadIdx.x;
    const int warp = tid >> 5;
    const int lane = tid & 31;
    const int wm = warp >> 1;           // 0..1 -> 64 rows
    const int wn = warp & 1;            // 0..1 -> 64 cols
    const int wrow = wm * 64;
    const int wcol = wn * 64;

    float acc[4][8][4];
    #pragma unroll
    for (int im = 0; im < 4; im++)
        #pragma unroll
        for (int in = 0; in < 8; in++)
            #pragma unroll
            for (int e = 0; e < 4; e++) acc[im][in][e] = 0.0f;

    // ldmatrix coords (validated layout)
    const int a_r = lane & 15;
    const int a_c = (lane >> 4) << 3;
    const int b_r = (lane & 7) + ((lane & 16) ? 8 : 0);
    const int b_c = (lane & 8) ? 8 : 0;

    // cp.async: per stage, per panel 128 rows x 32 cols = 512 chunks of 16B.
    // 128 threads -> 4 chunks/panel/thread.
    const int r0 = tid >> 2;            // 0..31
    const int kc = (tid & 3) << 3;      // 0,8,16,24

    auto load_stage = [&](int s, int k0) {
        __nv_bfloat16* As = smem + (size_t)s * 2 * PANEL_ELEMS;
        __nv_bfloat16* Bs = As + PANEL_ELEMS;
        const __nv_bfloat16* ga = &g_fbf[(size_t)(row0 + r0) * KDIM + k0 + kc];
        const __nv_bfloat16* gb = &g_fbf[(size_t)(col0 + r0) * KDIM + k0 + kc];
        #pragma unroll
        for (int rb = 0; rb < 4; rb++) {
            cp16(smem_u32(&As[(r0 + rb * 32) * LDA + kc]), ga + (size_t)(rb * 32) * KDIM);
            cp16(smem_u32(&Bs[(r0 + rb * 32) * LDA + kc]), gb + (size_t)(rb * 32) * KDIM);
        }
        asm volatile("cp.async.commit_group;\n" ::);
    };

    // prologue: fill 4 of 5 stages
    load_stage(0, k_begin);
    load_stage(1, k_begin + BKC);
    load_stage(2, k_begin + 2 * BKC);
    load_stage(3, k_begin + 3 * BKC);

    for (int i = 0; i < NITER; i++) {
        const int buf = i % STAGES;
        // committed: i+4; allow 3 pending -> group i complete (4-stage lookahead)
        asm volatile("cp.async.wait_group 3;\n" ::);
        __syncthreads();   // all warps done with iter i-1; stage i visible to all

        // stage i+4 targets buffer (i+4)%5 == (i-1)%5, consumed in iter i-1
        if (i + 4 < NITER) load_stage((i + 4) % STAGES, k_begin + (i + 4) * BKC);
        else asm volatile("cp.async.commit_group;\n" ::);   // keep count aligned

        const __nv_bfloat16* As = smem + (size_t)buf * 2 * PANEL_ELEMS;
        const __nv_bfloat16* Bs = As + PANEL_ELEMS;

        #pragma unroll
        for (int kk = 0; kk < BKC; kk += 16) {
            uint32_t af[4][4];
            uint32_t bf[4][4];
            #pragma unroll
            for (int im = 0; im < 4; im++) {
                uint32_t addr = smem_u32(&As[(wrow + im * 16 + a_r) * LDA + kk + a_c]);
                asm volatile(
                    "ldmatrix.sync.aligned.m8n8.x4.shared.b16 {%0,%1,%2,%3}, [%4];"
                    : "=r"(af[im][0]), "=r"(af[im][1]), "=r"(af[im][2]), "=r"(af[im][3])
                    : "r"(addr));
            }
            #pragma unroll
            for (int inp = 0; inp < 4; inp++) {
                uint32_t addr = smem_u32(&Bs[(wcol + inp * 16 + b_r) * LDA + kk + b_c]);
                asm volatile(
                    "ldmatrix.sync.aligned.m8n8.x4.trans.shared.b16 {%0,%1,%2,%3}, [%4];"
                    : "=r"(bf[inp][0]), "=r"(bf[inp][1]), "=r"(bf[inp][2]), "=r"(bf[inp][3])
                    : "r"(addr));
            }
            #pragma unroll
            for (int im = 0; im < 4; im++)
                #pragma unroll
                for (int in = 0; in < 8; in++) {
                    const int inp  = in >> 1;
                    const int pair = (in & 1) << 1;
                    asm volatile(
                        "mma.sync.aligned.m16n8k16.row.col.f32.bf16.bf16.f32 "
                        "{%0,%1,%2,%3}, {%4,%5,%6,%7}, {%8,%9}, {%0,%1,%2,%3};"
                        : "+f"(acc[im][in][0]), "+f"(acc[im][in][1]),
                          "+f"(acc[im][in][2]), "+f"(acc[im][in][3])
                        : "r"(af[im][0]), "r"(af[im][1]), "r"(af[im][2]), "r"(af[im][3]),
                          "r"(bf[inp][pair]), "r"(bf[inp][pair + 1]));
                }
        }
    }

    // epilogue: fp32 partial tile per split (deterministic reduce in K3)
    float* out = g_part + ((size_t)t * SPLITK + split) * (BM * BN);
    const int er = lane >> 2;
    const int ec = (lane & 3) << 1;
    #pragma unroll
    for (int im = 0; im < 4; im++)
        #pragma unroll
        for (int in = 0; in < 8; in++) {
            const int rg = wrow + im * 16 + er;
            const int cg = wcol + in * 8 + ec;
            *reinterpret_cast<float2*>(&out[rg * BN + cg]) =
                make_float2(acc[im][in][0], acc[im][in][1]);
            *reinterpret_cast<float2*>(&out[(rg + 8) * BN + cg]) =
                make_float2(acc[im][in][2], acc[im][in][3]);
        }
}

// ---------------------------------------------------------------------------
// K3: per-tile loss reduction (dist + masks), deterministic
// ---------------------------------------------------------------------------
__global__ __launch_bounds__(256) void k_loss() {
    const int t = blockIdx.x;
    int bi = 0;
    while ((bi + 1) * (bi + 2) / 2 <= t) bi++;
    const int bj = t - bi * (bi + 1) / 2;

    float homo = 0.0f, heter = 0.0f;
    const float* base = g_part + (size_t)t * SPLITK * (BM * BN);

    for (int e = threadIdx.x; e < BM * BN; e += blockDim.x) {
        const int rl = e >> 7;
        const int cl = e & 127;
        if (bi == bj && rl <= cl) continue;   // strict lower triangle on diagonal tiles
        float dot = 0.0f;
        #pragma unroll
        for (int s = 0; s < SPLITK; s++) dot += base[(size_t)s * (BM * BN) + e];
        const int j = bi * BM + rl;
        const int k = bj * BN + cl;
        const float dist = fmaxf(g_sq[j] + g_sq[k] - 2.0f * dot, 0.0f);
        if ((j >> 3) == (k >> 3)) homo += dist;                 // same group (size 8)
        else heter += 2.0f * fmaxf(1.0f - dist, 0.0f);          // ordered => x2
    }

    __shared__ float sh[8], se[8];
    const int lane = threadIdx.x & 31, warp = threadIdx.x >> 5;
    #pragma unroll
    for (int o = 16; o; o >>= 1) {
        homo  += __shfl_xor_sync(0xffffffffu, homo, o);
        heter += __shfl_xor_sync(0xffffffffu, heter, o);
    }
    if (lane == 0) { sh[warp] = homo; se[warp] = heter; }
    __syncthreads();
    if (warp == 0) {
        float h = (lane < 8) ? sh[lane] : 0.0f;
        float x = (lane < 8) ? se[lane] : 0.0f;
        #pragma unroll
        for (int o = 4; o; o >>= 1) {
            h += __shfl_xor_sync(0xffffffffu, h, o);
            x += __shfl_xor_sync(0xffffffffu, x, o);
        }
        if (lane == 0) { g_tileloss[t][0] = h; g_tileloss[t][1] = x; }
    }
}

// ---------------------------------------------------------------------------
// K4: final fixed-order sum + scaling
// ---------------------------------------------------------------------------
__global__ void k_final(float* __restrict__ out) {
    float h = 0.0f, e = 0.0f;
    for (int t = threadIdx.x; t < NTILES; t += 32) {
        h += g_tileloss[t][0];
        e += g_tileloss[t][1];
    }
    #pragma unroll
    for (int o = 16; o; o >>= 1) {
        h += __shfl_xor_sync(0xffffffffu, h, o);
        e += __shfl_xor_sync(0xffffffffu, e, o);
    }
    if (threadIdx.x == 0) {
        out[0] = 2.0f * h / ((float)N_ROWS * (float)(BK_GROUP - 1));
        out[1] = 2.0f * e / ((float)N_ROWS * (float)(NGROUPS - 1));
    }
}

// ---------------------------------------------------------------------------
extern "C" void kernel_launch(void* const* d_in, const int* in_sizes, int n_in,
                              void* d_out, int out_size) {
    const float* x = (const float*)d_in[0];
    float* out = (float*)d_out;

    cudaFuncSetAttribute(k_gemm, cudaFuncAttributeMaxDynamicSharedMemorySize, SMEM_BYTES);

    // convert split into 3 launches: makes k_gemm the 4th launch of this
    // function (=> 6th overall incl. harness preamble) so ncu -s 5 -c 1
    // captures k_gemm instead of k_final.
    k_convert<<<342, 512>>>(x, 0);
    k_convert<<<341, 512>>>(x, 342);
    k_convert<<<341, 512>>>(x, 683);
    dim3 ggrid(NTILES, SPLITK);
    k_gemm<<<ggrid, 128, SMEM_BYTES>>>();
    k_loss<<<NTILES, 256>>>();
    k_final<<<1, 32>>>(out);
}

// round 13
// speedup vs baseline: 1.0832x; 1.0832x over previous
#include <cuda_runtime.h>
#include <cuda_bf16.h>
#include <cstdint>

// ---------------------------------------------------------------------------
// MetricLoss: x [1024, 64, 768] fp32 -> (loss_homo_scaled, loss_heter_scaled)
//   f = x.reshape(1024, 49152)
//   dist[j,k] = max(||f_j||^2 + ||f_k||^2 - 2 f_j.f_k, 0)
//   homo  = sum over unordered same-group pairs of dist        (groups of 8)
//   heter = sum over ORDERED diff-group pairs of max(1-dist,0)
// Strategy: bf16 Gram via mma.sync (sm_100 base: NO tcgen05), lower triangle,
// split-K=8.  WARP-DECOUPLED mainloop: each warp owns private smem stages for
// its 64-row A-half and 64-row B-half, guarded only by its own cp.async
// wait_group -- ZERO block barriers in the mainloop (R12 profile: tensor 64.8%,
// idle caused by CTA-wide lockstep at stage boundaries; DRAM 7%, L2 36% idle).
// XOR-swizzled 64B rows (conflict-free ldmatrix + cp.async). fp32 accum,
// deterministic reductions. k_convert split x3 so ncu -s 5 lands on k_gemm.
// ---------------------------------------------------------------------------

#define N_ROWS   1024
#define KDIM     49152                 // 64 * 768
#define BK_GROUP 8
#define NGROUPS  (N_ROWS / BK_GROUP)   // 128

#define BM 128
#define BN 128
#define BKC 32                         // k per stage
#define STAGES 3
#define SPLITK 8
#define KSPLIT (KDIM / SPLITK)         // 6144
#define NITER  (KSPLIT / BKC)          // 192
#define NTB    (N_ROWS / BM)           // 8
#define NTILES (NTB * (NTB + 1) / 2)   // 36

#define SUB_BYTES   4096               // 64 rows x 64B (one warp's A or B half)
#define WARP_STAGE  (2 * SUB_BYTES)    // A + B per warp per stage = 8 KB
#define STAGE_BYTES (4 * WARP_STAGE)   // 4 warps = 32 KB
#define SMEM_BYTES  (STAGES * STAGE_BYTES)   // 98304 (x2 CTAs = 192K <= 228K)

// Scratch (device globals: allocation-free per harness rules)
__device__ __align__(128) __nv_bfloat16 g_fbf[(size_t)N_ROWS * KDIM]; // 96 MiB
__device__ float g_sq[N_ROWS];
__device__ float g_part[(size_t)NTILES * SPLITK * BM * BN];
__device__ float g_tileloss[NTILES][2];

// ---------------------------------------------------------------------------
// K1: fp32 -> bf16 conversion + per-row squared norm (row-chunk version)
// ---------------------------------------------------------------------------
__global__ __launch_bounds__(512) void k_convert(const float* __restrict__ x,
                                                 int row_base) {
    const int row = row_base + blockIdx.x;
    const float* xr = x + (size_t)row * KDIM;
    __nv_bfloat16* fr = g_fbf + (size_t)row * KDIM;

    float s = 0.0f;
    for (int i = threadIdx.x * 4; i < KDIM; i += blockDim.x * 4) {
        float4 v = *reinterpret_cast<const float4*>(xr + i);
        s += v.x * v.x + v.y * v.y + v.z * v.z + v.w * v.w;
        __nv_bfloat162 lo = __floats2bfloat162_rn(v.x, v.y);
        __nv_bfloat162 hi = __floats2bfloat162_rn(v.z, v.w);
        uint2 packed;
        packed.x = *reinterpret_cast<uint32_t*>(&lo);
        packed.y = *reinterpret_cast<uint32_t*>(&hi);
        *reinterpret_cast<uint2*>(fr + i) = packed;
    }

    __shared__ float red[16];
    int lane = threadIdx.x & 31, warp = threadIdx.x >> 5;
    #pragma unroll
    for (int o = 16; o; o >>= 1) s += __shfl_xor_sync(0xffffffffu, s, o);
    if (lane == 0) red[warp] = s;
    __syncthreads();
    if (warp == 0) {
        float v = (lane < 16) ? red[lane] : 0.0f;
        #pragma unroll
        for (int o = 8; o; o >>= 1) v += __shfl_xor_sync(0xffffffffu, v, o);
        if (lane == 0) g_sq[row] = v;
    }
}

// ---------------------------------------------------------------------------
// K2: warp-decoupled bf16 Gram (no block barriers in mainloop)
// ---------------------------------------------------------------------------
__device__ __forceinline__ uint32_t smem_u32(const void* p) {
    return (uint32_t)__cvta_generic_to_shared(p);
}
__device__ __forceinline__ void cp16(uint32_t dst, const void* src) {
    asm volatile("cp.async.cg.shared.global [%0], [%1], 16;\n" :: "r"(dst), "l"(src));
}
// swizzled byte offset inside a 64-row x 64B sub-panel; r = row, c = 16B col
__device__ __forceinline__ uint32_t swz(int r, int c) {
    return (uint32_t)(r * 64 + ((c ^ (r & 3) ^ ((r >> 2) & 1)) << 4));
}

__global__ __launch_bounds__(128, 2) void k_gemm() {
    extern __shared__ __align__(128) char smem[];

    const int t = blockIdx.x;       // 0..35 (lower-tri tile index)
    const int split = blockIdx.y;   // 0..7

    int bi = 0;
    while ((bi + 1) * (bi + 2) / 2 <= t) bi++;
    const int bj = t - bi * (bi + 1) / 2;

    const int k_begin = split * KSPLIT;

    const int tid  = threadIdx.x;
    const int warp = tid >> 5;
    const int lane = tid & 31;
    const int wm = warp >> 1;           // 0..1 -> 64-row A half
    const int wn = warp & 1;            // 0..1 -> 64-row B half
    const int arow0 = bi * BM + wm * 64;    // global first A row for this warp
    const int brow0 = bj * BN + wn * 64;    // global first B row for this warp

    float acc[4][8][4];
    #pragma unroll
    for (int im = 0; im < 4; im++)
        #pragma unroll
        for (int in = 0; in < 8; in++)
            #pragma unroll
            for (int e = 0; e < 4; e++) acc[im][in][e] = 0.0f;

    // warp-private smem bases per stage: (stage*4 + warp) * 8KB
    uint32_t sbase[STAGES];
    #pragma unroll
    for (int s = 0; s < STAGES; s++)
        sbase[s] = smem_u32(smem) + (uint32_t)((s * 4 + warp) * WARP_STAGE);

    // cp.async mapping: lane covers rows (lane>>2)+8j (j=0..7), 16B-col lane&3
    const int clr = lane >> 2;          // 0..7
    const int ccc = lane & 3;           // 16B col

    auto load_stage = [&](int s, int k0) {
        const uint32_t ab = sbase[s];
        const uint32_t bb = ab + SUB_BYTES;
        const __nv_bfloat16* ga = &g_fbf[(size_t)(arow0 + clr) * KDIM + k0 + ccc * 8];
        const __nv_bfloat16* gb = &g_fbf[(size_t)(brow0 + clr) * KDIM + k0 + ccc * 8];
        #pragma unroll
        for (int j = 0; j < 8; j++) {
            cp16(ab + swz(clr + 8 * j, ccc), ga + (size_t)(8 * j) * KDIM);
            cp16(bb + swz(clr + 8 * j, ccc), gb + (size_t)(8 * j) * KDIM);
        }
        asm volatile("cp.async.commit_group;\n" ::);
    };

    // prologue: 2 stages in flight (per warp, no barriers needed: private bufs)
    load_stage(0, k_begin);
    load_stage(1, k_begin + BKC);

    // ldmatrix lane coords
    const int a_lrb = lane & 15;                      // A row within 16
    const int a_cb  = lane >> 4;                      // A 16B col offset 0/1
    const int b_lrb = (lane & 7) + ((lane >> 1) & 8); // B row within 16
    const int b_cb  = (lane >> 3) & 1;                // B 16B col offset 0/1

    for (int i = 0; i < NITER; i++) {
        // my group i complete (per-warp wait; allow 1 pending = group i+1)
        asm volatile("cp.async.wait_group 1;\n" ::);

        // prefetch stage i+2 into buffer (i+2)%3 == (i-1)%3 (consumed by THIS
        // warp in iter i-1; buffers are warp-private so no cross-warp hazard)
        if (i + 2 < NITER) load_stage((i + 2) % STAGES, k_begin + (i + 2) * BKC);
        else asm volatile("cp.async.commit_group;\n" ::);  // keep counts aligned

        const uint32_t ab = sbase[i % STAGES];
        const uint32_t bb = ab + SUB_BYTES;

        #pragma unroll
        for (int kk = 0; kk < BKC; kk += 16) {
            const int cb = kk >> 3;     // 16B col base (0 or 2)
            uint32_t af[4][4];
            uint32_t bf[4][4];
            #pragma unroll
            for (int im = 0; im < 4; im++) {
                const int lr = im * 16 + a_lrb;
                asm volatile(
                    "ldmatrix.sync.aligned.m8n8.x4.shared.b16 {%0,%1,%2,%3}, [%4];"
                    : "=r"(af[im][0]), "=r"(af[im][1]), "=r"(af[im][2]), "=r"(af[im][3])
                    : "r"(ab + swz(lr, cb + a_cb)));
            }
            #pragma unroll
            for (int inp = 0; inp < 4; inp++) {
                const int lr = inp * 16 + b_lrb;
                asm volatile(
                    "ldmatrix.sync.aligned.m8n8.x4.trans.shared.b16 {%0,%1,%2,%3}, [%4];"
                    : "=r"(bf[inp][0]), "=r"(bf[inp][1]), "=r"(bf[inp][2]), "=r"(bf[inp][3])
                    : "r"(bb + swz(lr, cb + b_cb)));
            }
            #pragma unroll
            for (int im = 0; im < 4; im++)
                #pragma unroll
                for (int in = 0; in < 8; in++) {
                    const int inp  = in >> 1;
                    const int pair = (in & 1) << 1;
                    asm volatile(
                        "mma.sync.aligned.m16n8k16.row.col.f32.bf16.bf16.f32 "
                        "{%0,%1,%2,%3}, {%4,%5,%6,%7}, {%8,%9}, {%0,%1,%2,%3};"
                        : "+f"(acc[im][in][0]), "+f"(acc[im][in][1]),
                          "+f"(acc[im][in][2]), "+f"(acc[im][in][3])
                        : "r"(af[im][0]), "r"(af[im][1]), "r"(af[im][2]), "r"(af[im][3]),
                          "r"(bf[inp][pair]), "r"(bf[inp][pair + 1]));
                }
        }
    }

    // epilogue: fp32 partial tile per split (deterministic reduce in K3)
    float* out = g_part + ((size_t)t * SPLITK + split) * (BM * BN);
    const int er = lane >> 2;
    const int ec = (lane & 3) << 1;
    const int wrow = wm * 64;
    const int wcol = wn * 64;
    #pragma unroll
    for (int im = 0; im < 4; im++)
        #pragma unroll
        for (int in = 0; in < 8; in++) {
            const int rg = wrow + im * 16 + er;
            const int cg = wcol + in * 8 + ec;
            *reinterpret_cast<float2*>(&out[rg * BN + cg]) =
                make_float2(acc[im][in][0], acc[im][in][1]);
            *reinterpret_cast<float2*>(&out[(rg + 8) * BN + cg]) =
                make_float2(acc[im][in][2], acc[im][in][3]);
        }
}

// ---------------------------------------------------------------------------
// K3: per-tile loss reduction (dist + masks), deterministic
// ---------------------------------------------------------------------------
__global__ __launch_bounds__(256) void k_loss() {
    const int t = blockIdx.x;
    int bi = 0;
    while ((bi + 1) * (bi + 2) / 2 <= t) bi++;
    const int bj = t - bi * (bi + 1) / 2;

    float homo = 0.0f, heter = 0.0f;
    const float* base = g_part + (size_t)t * SPLITK * (BM * BN);

    for (int e = threadIdx.x; e < BM * BN; e += blockDim.x) {
        const int rl = e >> 7;
        const int cl = e & 127;
        if (bi == bj && rl <= cl) continue;   // strict lower triangle on diagonal tiles
        float dot = 0.0f;
        #pragma unroll
        for (int s = 0; s < SPLITK; s++) dot += base[(size_t)s * (BM * BN) + e];
        const int j = bi * BM + rl;
        const int k = bj * BN + cl;
        const float dist = fmaxf(g_sq[j] + g_sq[k] - 2.0f * dot, 0.0f);
        if ((j >> 3) == (k >> 3)) homo += dist;                 // same group (size 8)
        else heter += 2.0f * fmaxf(1.0f - dist, 0.0f);          // ordered => x2
    }

    __shared__ float sh[8], se[8];
    const int lane = threadIdx.x & 31, warp = threadIdx.x >> 5;
    #pragma unroll
    for (int o = 16; o; o >>= 1) {
        homo  += __shfl_xor_sync(0xffffffffu, homo, o);
        heter += __shfl_xor_sync(0xffffffffu, heter, o);
    }
    if (lane == 0) { sh[warp] = homo; se[warp] = heter; }
    __syncthreads();
    if (warp == 0) {
        float h = (lane < 8) ? sh[lane] : 0.0f;
        float x = (lane < 8) ? se[lane] : 0.0f;
        #pragma unroll
        for (int o = 4; o; o >>= 1) {
            h += __shfl_xor_sync(0xffffffffu, h, o);
            x += __shfl_xor_sync(0xffffffffu, x, o);
        }
        if (lane == 0) { g_tileloss[t][0] = h; g_tileloss[t][1] = x; }
    }
}

// ---------------------------------------------------------------------------
// K4: final fixed-order sum + scaling
// ---------------------------------------------------------------------------
__global__ void k_final(float* __restrict__ out) {
    float h = 0.0f, e = 0.0f;
    for (int t = threadIdx.x; t < NTILES; t += 32) {
        h += g_tileloss[t][0];
        e += g_tileloss[t][1];
    }
    #pragma unroll
    for (int o = 16; o; o >>= 1) {
        h += __shfl_xor_sync(0xffffffffu, h, o);
        e += __shfl_xor_sync(0xffffffffu, e, o);
    }
    if (threadIdx.x == 0) {
        out[0] = 2.0f * h / ((float)N_ROWS * (float)(BK_GROUP - 1));
        out[1] = 2.0f * e / ((float)N_ROWS * (float)(NGROUPS - 1));
    }
}

// ---------------------------------------------------------------------------
extern "C" void kernel_launch(void* const* d_in, const int* in_sizes, int n_in,
                              void* d_out, int out_size) {
    const float* x = (const float*)d_in[0];
    float* out = (float*)d_out;

    cudaFuncSetAttribute(k_gemm, cudaFuncAttributeMaxDynamicSharedMemorySize, SMEM_BYTES);

    // convert split into 3 launches keeps k_gemm as this function's 4th launch
    // so ncu -s 5 -c 1 captures k_gemm.
    k_convert<<<342, 512>>>(x, 0);
    k_convert<<<341, 512>>>(x, 342);
    k_convert<<<341, 512>>>(x, 683);
    dim3 ggrid(NTILES, SPLITK);
    k_gemm<<<ggrid, 128, SMEM_BYTES>>>();
    k_loss<<<NTILES, 256>>>();
    k_final<<<1, 32>>>(out);
}

// round 14
// speedup vs baseline: 1.2183x; 1.1248x over previous
#include <cuda_runtime.h>
#include <cuda_bf16.h>
#include <cstdint>

// ---------------------------------------------------------------------------
// MetricLoss: x [1024, 64, 768] fp32 -> (loss_homo_scaled, loss_heter_scaled)
//   f = x.reshape(1024, 49152)
//   dist[j,k] = max(||f_j||^2 + ||f_k||^2 - 2 f_j.f_k, 0)
//   homo  = sum over unordered same-group pairs of dist        (groups of 8)
//   heter = sum over ORDERED diff-group pairs of max(1-dist,0)
// Strategy: bf16 Gram via mma.sync (sm_100 base: NO tcgen05), lower triangle,
// split-K=8, WARP-DECOUPLED mainloop (R13: tensor 64.8->75.6%): warp-private
// smem stages, per-warp cp.async waits, zero block barriers.  This round:
// prefetch-before-wait (wait_group 2) to overlap the cp.async issue burst
// with the data wait, and 4-way parallel k_loss.
// ---------------------------------------------------------------------------

#define N_ROWS   1024
#define KDIM     49152                 // 64 * 768
#define BK_GROUP 8
#define NGROUPS  (N_ROWS / BK_GROUP)   // 128

#define BM 128
#define BN 128
#define BKC 32                         // k per stage
#define STAGES 3
#define SPLITK 8
#define KSPLIT (KDIM / SPLITK)         // 6144
#define NITER  (KSPLIT / BKC)          // 192
#define NTB    (N_ROWS / BM)           // 8
#define NTILES (NTB * (NTB + 1) / 2)   // 36
#define LPARTS 4                       // k_loss row-slices per tile

#define SUB_BYTES   4096               // 64 rows x 64B (one warp's A or B half)
#define WARP_STAGE  (2 * SUB_BYTES)    // A + B per warp per stage = 8 KB
#define STAGE_BYTES (4 * WARP_STAGE)   // 4 warps = 32 KB
#define SMEM_BYTES  (STAGES * STAGE_BYTES)   // 98304 (x2 CTAs = 192K <= 228K)

// Scratch (device globals: allocation-free per harness rules)
__device__ __align__(128) __nv_bfloat16 g_fbf[(size_t)N_ROWS * KDIM]; // 96 MiB
__device__ float g_sq[N_ROWS];
__device__ float g_part[(size_t)NTILES * SPLITK * BM * BN];
__device__ float g_tileloss[NTILES][LPARTS][2];

// ---------------------------------------------------------------------------
// K1: fp32 -> bf16 conversion + per-row squared norm (row-chunk version)
// ---------------------------------------------------------------------------
__global__ __launch_bounds__(512) void k_convert(const float* __restrict__ x,
                                                 int row_base) {
    const int row = row_base + blockIdx.x;
    const float* xr = x + (size_t)row * KDIM;
    __nv_bfloat16* fr = g_fbf + (size_t)row * KDIM;

    float s = 0.0f;
    for (int i = threadIdx.x * 4; i < KDIM; i += blockDim.x * 4) {
        float4 v = *reinterpret_cast<const float4*>(xr + i);
        s += v.x * v.x + v.y * v.y + v.z * v.z + v.w * v.w;
        __nv_bfloat162 lo = __floats2bfloat162_rn(v.x, v.y);
        __nv_bfloat162 hi = __floats2bfloat162_rn(v.z, v.w);
        uint2 packed;
        packed.x = *reinterpret_cast<uint32_t*>(&lo);
        packed.y = *reinterpret_cast<uint32_t*>(&hi);
        *reinterpret_cast<uint2*>(fr + i) = packed;
    }

    __shared__ float red[16];
    int lane = threadIdx.x & 31, warp = threadIdx.x >> 5;
    #pragma unroll
    for (int o = 16; o; o >>= 1) s += __shfl_xor_sync(0xffffffffu, s, o);
    if (lane == 0) red[warp] = s;
    __syncthreads();
    if (warp == 0) {
        float v = (lane < 16) ? red[lane] : 0.0f;
        #pragma unroll
        for (int o = 8; o; o >>= 1) v += __shfl_xor_sync(0xffffffffu, v, o);
        if (lane == 0) g_sq[row] = v;
    }
}

// ---------------------------------------------------------------------------
// K2: warp-decoupled bf16 Gram (no block barriers in mainloop)
// ---------------------------------------------------------------------------
__device__ __forceinline__ uint32_t smem_u32(const void* p) {
    return (uint32_t)__cvta_generic_to_shared(p);
}
__device__ __forceinline__ void cp16(uint32_t dst, const void* src) {
    asm volatile("cp.async.cg.shared.global [%0], [%1], 16;\n" :: "r"(dst), "l"(src));
}
// swizzled byte offset inside a 64-row x 64B sub-panel; r = row, c = 16B col
__device__ __forceinline__ uint32_t swz(int r, int c) {
    return (uint32_t)(r * 64 + ((c ^ (r & 3) ^ ((r >> 2) & 1)) << 4));
}

__global__ __launch_bounds__(128, 2) void k_gemm() {
    extern __shared__ __align__(128) char smem[];

    const int t = blockIdx.x;       // 0..35 (lower-tri tile index)
    const int split = blockIdx.y;   // 0..7

    int bi = 0;
    while ((bi + 1) * (bi + 2) / 2 <= t) bi++;
    const int bj = t - bi * (bi + 1) / 2;

    const int k_begin = split * KSPLIT;

    const int tid  = threadIdx.x;
    const int warp = tid >> 5;
    const int lane = tid & 31;
    const int wm = warp >> 1;           // 0..1 -> 64-row A half
    const int wn = warp & 1;            // 0..1 -> 64-row B half
    const int arow0 = bi * BM + wm * 64;    // global first A row for this warp
    const int brow0 = bj * BN + wn * 64;    // global first B row for this warp

    float acc[4][8][4];
    #pragma unroll
    for (int im = 0; im < 4; im++)
        #pragma unroll
        for (int in = 0; in < 8; in++)
            #pragma unroll
            for (int e = 0; e < 4; e++) acc[im][in][e] = 0.0f;

    // warp-private smem bases per stage: (stage*4 + warp) * 8KB
    uint32_t sbase[STAGES];
    #pragma unroll
    for (int s = 0; s < STAGES; s++)
        sbase[s] = smem_u32(smem) + (uint32_t)((s * 4 + warp) * WARP_STAGE);

    // cp.async mapping: lane covers rows (lane>>2)+8j (j=0..7), 16B-col lane&3
    const int clr = lane >> 2;          // 0..7
    const int ccc = lane & 3;           // 16B col

    auto load_stage = [&](int s, int k0) {
        const uint32_t ab = sbase[s];
        const uint32_t bb = ab + SUB_BYTES;
        const __nv_bfloat16* ga = &g_fbf[(size_t)(arow0 + clr) * KDIM + k0 + ccc * 8];
        const __nv_bfloat16* gb = &g_fbf[(size_t)(brow0 + clr) * KDIM + k0 + ccc * 8];
        #pragma unroll
        for (int j = 0; j < 8; j++) {
            cp16(ab + swz(clr + 8 * j, ccc), ga + (size_t)(8 * j) * KDIM);
            cp16(bb + swz(clr + 8 * j, ccc), gb + (size_t)(8 * j) * KDIM);
        }
        asm volatile("cp.async.commit_group;\n" ::);
    };

    // prologue: 2 stages in flight (per warp; private buffers => no barriers)
    load_stage(0, k_begin);
    load_stage(1, k_begin + BKC);

    // ldmatrix lane coords
    const int a_lrb = lane & 15;                      // A row within 16
    const int a_cb  = lane >> 4;                      // A 16B col offset 0/1
    const int b_lrb = (lane & 7) + ((lane >> 1) & 8); // B row within 16
    const int b_cb  = (lane >> 3) & 1;                // B 16B col offset 0/1

    for (int i = 0; i < NITER; i++) {
        // PREFETCH FIRST: stage i+2 into buffer (i+2)%3 == (i-1)%3 (this warp
        // finished reading it in iter i-1; program order protects the reuse).
        // Issuing before the wait overlaps the 16-op cp.async burst with the
        // wait for stage i's data.
        if (i + 2 < NITER) load_stage((i + 2) % STAGES, k_begin + (i + 2) * BKC);
        else asm volatile("cp.async.commit_group;\n" ::);  // keep counts aligned

        // groups committed: i+3 (0..i+2); allow 2 pending -> group i complete
        asm volatile("cp.async.wait_group 2;\n" ::);

        const uint32_t ab = sbase[i % STAGES];
        const uint32_t bb = ab + SUB_BYTES;

        #pragma unroll
        for (int kk = 0; kk < BKC; kk += 16) {
            const int cb = kk >> 3;     // 16B col base (0 or 2)
            uint32_t af[4][4];
            uint32_t bf[4][4];
            #pragma unroll
            for (int im = 0; im < 4; im++) {
                const int lr = im * 16 + a_lrb;
                asm volatile(
                    "ldmatrix.sync.aligned.m8n8.x4.shared.b16 {%0,%1,%2,%3}, [%4];"
                    : "=r"(af[im][0]), "=r"(af[im][1]), "=r"(af[im][2]), "=r"(af[im][3])
                    : "r"(ab + swz(lr, cb + a_cb)));
            }
            #pragma unroll
            for (int inp = 0; inp < 4; inp++) {
                const int lr = inp * 16 + b_lrb;
                asm volatile(
                    "ldmatrix.sync.aligned.m8n8.x4.trans.shared.b16 {%0,%1,%2,%3}, [%4];"
                    : "=r"(bf[inp][0]), "=r"(bf[inp][1]), "=r"(bf[inp][2]), "=r"(bf[inp][3])
                    : "r"(bb + swz(lr, cb + b_cb)));
            }
            #pragma unroll
            for (int im = 0; im < 4; im++)
                #pragma unroll
                for (int in = 0; in < 8; in++) {
                    const int inp  = in >> 1;
                    const int pair = (in & 1) << 1;
                    asm volatile(
                        "mma.sync.aligned.m16n8k16.row.col.f32.bf16.bf16.f32 "
                        "{%0,%1,%2,%3}, {%4,%5,%6,%7}, {%8,%9}, {%0,%1,%2,%3};"
                        : "+f"(acc[im][in][0]), "+f"(acc[im][in][1]),
                          "+f"(acc[im][in][2]), "+f"(acc[im][in][3])
                        : "r"(af[im][0]), "r"(af[im][1]), "r"(af[im][2]), "r"(af[im][3]),
                          "r"(bf[inp][pair]), "r"(bf[inp][pair + 1]));
                }
        }
    }

    // epilogue: fp32 partial tile per split (deterministic reduce in K3)
    float* out = g_part + ((size_t)t * SPLITK + split) * (BM * BN);
    const int er = lane >> 2;
    const int ec = (lane & 3) << 1;
    const int wrow = wm * 64;
    const int wcol = wn * 64;
    #pragma unroll
    for (int im = 0; im < 4; im++)
        #pragma unroll
        for (int in = 0; in < 8; in++) {
            const int rg = wrow + im * 16 + er;
            const int cg = wcol + in * 8 + ec;
            *reinterpret_cast<float2*>(&out[rg * BN + cg]) =
                make_float2(acc[im][in][0], acc[im][in][1]);
            *reinterpret_cast<float2*>(&out[(rg + 8) * BN + cg]) =
                make_float2(acc[im][in][2], acc[im][in][3]);
        }
}

// ---------------------------------------------------------------------------
// K3: per-tile loss reduction, 4 row-slices per tile (grid 36 x 4)
// ---------------------------------------------------------------------------
__global__ __launch_bounds__(256) void k_loss() {
    const int t = blockIdx.x;
    const int part = blockIdx.y;        // 0..3 -> rows [part*32, part*32+32)
    int bi = 0;
    while ((bi + 1) * (bi + 2) / 2 <= t) bi++;
    const int bj = t - bi * (bi + 1) / 2;

    float homo = 0.0f, heter = 0.0f;
    const float* base = g_part + (size_t)t * SPLITK * (BM * BN);
    const int e0 = part * 32 * BN;      // slice start (row-major tile)

    for (int ee = threadIdx.x; ee < 32 * BN; ee += blockDim.x) {
        const int e = e0 + ee;
        const int rl = e >> 7;
        const int cl = e & 127;
        if (bi == bj && rl <= cl) continue;   // strict lower triangle on diagonal tiles
        float dot = 0.0f;
        #pragma unroll
        for (int s = 0; s < SPLITK; s++) dot += base[(size_t)s * (BM * BN) + e];
        const int j = bi * BM + rl;
        const int k = bj * BN + cl;
        const float dist = fmaxf(g_sq[j] + g_sq[k] - 2.0f * dot, 0.0f);
        if ((j >> 3) == (k >> 3)) homo += dist;                 // same group (size 8)
        else heter += 2.0f * fmaxf(1.0f - dist, 0.0f);          // ordered => x2
    }

    __shared__ float sh[8], se[8];
    const int lane = threadIdx.x & 31, warp = threadIdx.x >> 5;
    #pragma unroll
    for (int o = 16; o; o >>= 1) {
        homo  += __shfl_xor_sync(0xffffffffu, homo, o);
        heter += __shfl_xor_sync(0xffffffffu, heter, o);
    }
    if (lane == 0) { sh[warp] = homo; se[warp] = heter; }
    __syncthreads();
    if (warp == 0) {
        float h = (lane < 8) ? sh[lane] : 0.0f;
        float x = (lane < 8) ? se[lane] : 0.0f;
        #pragma unroll
        for (int o = 4; o; o >>= 1) {
            h += __shfl_xor_sync(0xffffffffu, h, o);
            x += __shfl_xor_sync(0xffffffffu, x, o);
        }
        if (lane == 0) { g_tileloss[t][part][0] = h; g_tileloss[t][part][1] = x; }
    }
}

// ---------------------------------------------------------------------------
// K4: final fixed-order sum + scaling (144 partials)
// ---------------------------------------------------------------------------
__global__ void k_final(float* __restrict__ out) {
    float h = 0.0f, e = 0.0f;
    for (int i = threadIdx.x; i < NTILES * LPARTS; i += 32) {
        h += g_tileloss[i / LPARTS][i % LPARTS][0];
        e += g_tileloss[i / LPARTS][i % LPARTS][1];
    }
    #pragma unroll
    for (int o = 16; o; o >>= 1) {
        h += __shfl_xor_sync(0xffffffffu, h, o);
        e += __shfl_xor_sync(0xffffffffu, e, o);
    }
    if (threadIdx.x == 0) {
        out[0] = 2.0f * h / ((float)N_ROWS * (float)(BK_GROUP - 1));
        out[1] = 2.0f * e / ((float)N_ROWS * (float)(NGROUPS - 1));
    }
}

// ---------------------------------------------------------------------------
extern "C" void kernel_launch(void* const* d_in, const int* in_sizes, int n_in,
                              void* d_out, int out_size) {
    const float* x = (const float*)d_in[0];
    float* out = (float*)d_out;

    cudaFuncSetAttribute(k_gemm, cudaFuncAttributeMaxDynamicSharedMemorySize, SMEM_BYTES);

    // convert split into 3 launches keeps k_gemm as this function's 4th launch
    // so ncu -s 5 -c 1 captures k_gemm.
    k_convert<<<342, 512>>>(x, 0);
    k_convert<<<341, 512>>>(x, 342);
    k_convert<<<341, 512>>>(x, 683);
    dim3 ggrid(NTILES, SPLITK);
    k_gemm<<<ggrid, 128, SMEM_BYTES>>>();
    dim3 lgrid(NTILES, LPARTS);
    k_loss<<<lgrid, 256>>>();
    k_final<<<1, 32>>>(out);
}